// round 5
// baseline (speedup 1.0000x reference)
#include <cuda_runtime.h>
#include <cstdint>

#define MAXB 65536
#define BLK 256
#define EPT 4
#define TILE (BLK * EPT)                 // 1024 batches per scan tile
#define MAXG ((MAXB + TILE - 1) / TILE)  // 64 tiles

// Scratch (allocation-free, __device__ globals).
// meta: os(26) | ns(26)<<26 | f(10)<<52     per batch
__device__ unsigned long long g_meta[MAXB];
__device__ unsigned long long g_agg[MAXG];       // packed tile sums
__device__ int g_flags[2 * MAXG];                // [0,G): agg ready  [G,2G): meta ready

__device__ __forceinline__ unsigned long long pack2(int span, int filt) {
    return (unsigned long long)(unsigned int)span |
           ((unsigned long long)(unsigned int)filt << 32);
}

__global__ void __launch_bounds__(BLK) fused_kernel(
        const float* __restrict__ src,
        const int* __restrict__ al,
        const int* __restrict__ alf,
        float* __restrict__ out,
        int B, int G) {
    const int t = threadIdx.x, lane = t & 31, wid = t >> 5;
    const int bid = blockIdx.x;

    volatile int* agg_flag  = g_flags;
    volatile int* meta_flag = g_flags + MAXG;

    // ============================ SCAN PHASE ============================
    if (bid < G) {
        __shared__ unsigned long long s_wexcl[BLK / 32];
        __shared__ unsigned long long s_base;

        int i0 = bid * TILE + t * EPT;

        unsigned long long p[EPT];
        if (i0 + 3 < B) {
            int4 a = *(const int4*)(al + i0);
            int4 f = *(const int4*)(alf + i0);
            p[0] = pack2(a.x + 1, f.x);
            p[1] = pack2(a.y + 1, f.y);
            p[2] = pack2(a.z + 1, f.z);
            p[3] = pack2(a.w + 1, f.w);
        } else {
            #pragma unroll
            for (int k = 0; k < EPT; k++) {
                int i = i0 + k;
                p[k] = (i < B) ? pack2(al[i] + 1, alf[i]) : 0ull;
            }
        }
        unsigned long long tot = p[0] + p[1] + p[2] + p[3];

        // warp-inclusive scan of per-thread totals
        unsigned long long incl = tot;
        #pragma unroll
        for (int o = 1; o < 32; o <<= 1) {
            unsigned long long n = __shfl_up_sync(0xffffffffu, incl, o);
            if (lane >= o) incl += n;
        }
        unsigned long long texcl = incl - tot;
        __shared__ unsigned long long s_wtot[BLK / 32];
        if (lane == 31) s_wtot[wid] = incl;
        __syncthreads();

        // warp 0: scan the 8 warp totals; lane 7 publishes block aggregate
        if (wid == 0) {
            unsigned long long v = (lane < BLK / 32) ? s_wtot[lane] : 0ull;
            unsigned long long inc = v;
            #pragma unroll
            for (int o = 1; o < BLK / 32; o <<= 1) {
                unsigned long long n = __shfl_up_sync(0xffffffffu, inc, o);
                if (lane >= o) inc += n;
            }
            if (lane < BLK / 32) s_wexcl[lane] = inc - v;
            if (lane == BLK / 32 - 1) {
                g_agg[bid] = inc;           // block total
                __threadfence();
                agg_flag[bid] = 1;
            }
        }
        // warp 1: lookback — sum all predecessor aggregates
        if (wid == 1) {
            unsigned long long v = 0;
            for (int j = lane; j < bid; j += 32) {
                while (agg_flag[j] == 0) __nanosleep(32);
                v += ((volatile unsigned long long*)g_agg)[j];
            }
            #pragma unroll
            for (int o = 16; o > 0; o >>= 1)
                v += __shfl_down_sync(0xffffffffu, v, o);
            if (lane == 0) s_base = v;
        }
        __syncthreads();

        unsigned long long run = s_base + s_wexcl[wid] + texcl;
        #pragma unroll
        for (int k = 0; k < EPT; k++) {
            int i = i0 + k;
            if (i < B) {
                unsigned long long os = run & 0xffffffffull;         // span prefix
                unsigned long long ns = run >> 32;                   // filter prefix
                unsigned long long fv = p[k] >> 32;                  // this batch's f
                g_meta[i] = os | (ns << 26) | (fv << 52);
                run += p[k];
            }
        }
        __syncthreads();
        if (t == 0) {
            __threadfence();
            meta_flag[bid] = 1;
        }
    }

    // ============================ COPY PHASE ============================
    int b = bid * (BLK / 32) + wid;      // one warp per batch
    if (b >= B) return;

    int tile = b >> 10;                  // TILE = 1024
    while (meta_flag[tile] == 0) __nanosleep(64);
    __threadfence();

    unsigned long long m = ((volatile unsigned long long*)g_meta)[b];
    int f = (int)(m >> 52);
    if (f == 0) return;
    const float* s = src + (int)(m & 0x3ffffffull);
    float*       d = out + (int)((m >> 26) & 0x3ffffffull);

    // All <=16 predicated streaming loads first (high MLP), then stores.
    float v[16];
    #pragma unroll
    for (int k = 0; k < 16; k++) {
        int i = lane + k * 32;
        v[k] = (i < f) ? __ldcs(s + i) : 0.0f;
    }
    #pragma unroll
    for (int k = 0; k < 16; k++) {
        int i = lane + k * 32;
        if (i < f) __stcs(d + i, v[k]);
    }
}

// ---------------------------------------------------------------------------
// Launch: memset flag array (captured graph node) + one fused kernel.
// ---------------------------------------------------------------------------
extern "C" void kernel_launch(void* const* d_in, const int* in_sizes, int n_in,
                              void* d_out, int out_size) {
    const float* tgt_cache_loc = (const float*)d_in[0];
    const int*   accept_length = (const int*)d_in[1];
    const int*   accept_filter = (const int*)d_in[2];
    (void)n_in; (void)out_size;

    int B = in_sizes[1];
    int G = (B + TILE - 1) / TILE;

    void* flags_ptr = nullptr;
    cudaGetSymbolAddress(&flags_ptr, g_flags);
    cudaMemsetAsync(flags_ptr, 0, sizeof(int) * 2 * MAXG, 0);

    int blocks = (B + (BLK / 32) - 1) / (BLK / 32);   // one warp per batch
    fused_kernel<<<blocks, BLK>>>(tgt_cache_loc, accept_length, accept_filter,
                                  (float*)d_out, B, G);
}

// round 8
// speedup vs baseline: 1.8573x; 1.8573x over previous
#include <cuda_runtime.h>
#include <cstdint>

#define MAXB 65536
#define BLK 256
#define EPT 4
#define TILE (BLK * EPT)                 // 1024 batches per scan tile
#define MAXG ((MAXB + TILE - 1) / TILE)  // 64 tiles

// Scratch (allocation-free __device__ globals).
// g_meta[b]: os_loc(20) | ns_loc(20)<<20 | f(10)<<40   (offsets local to tile)
// g_agg[t]:  packed tile totals: span_sum(lo32) | filter_sum(hi32)
__device__ unsigned long long g_meta[MAXB];
__device__ unsigned long long g_agg[MAXG];

__device__ __forceinline__ unsigned long long pack2(int span, int filt) {
    return (unsigned long long)(unsigned int)span |
           ((unsigned long long)(unsigned int)filt << 32);
}

// ---------------------------------------------------------------------------
// Scan kernel: grid = G (<=64). Per-tile local exclusive scan + tile totals.
// No cross-block communication: deterministic, replay-safe.
// ---------------------------------------------------------------------------
__global__ void __launch_bounds__(BLK) scan_kernel(
        const int* __restrict__ al, const int* __restrict__ alf, int B) {
    __shared__ unsigned long long s_wexcl[BLK / 32];
    __shared__ unsigned long long s_wtot[BLK / 32];

    const int t = threadIdx.x, lane = t & 31, wid = t >> 5;
    const int bid = blockIdx.x;
    const int i0 = bid * TILE + t * EPT;

    // Load and pack 4 elements per thread.
    unsigned long long p[EPT];
    if (i0 + 3 < B) {
        int4 a = *(const int4*)(al + i0);
        int4 f = *(const int4*)(alf + i0);
        p[0] = pack2(a.x + 1, f.x);
        p[1] = pack2(a.y + 1, f.y);
        p[2] = pack2(a.z + 1, f.z);
        p[3] = pack2(a.w + 1, f.w);
    } else {
        #pragma unroll
        for (int k = 0; k < EPT; k++) {
            int i = i0 + k;
            p[k] = (i < B) ? pack2(al[i] + 1, alf[i]) : 0ull;
        }
    }
    unsigned long long tot = p[0] + p[1] + p[2] + p[3];

    // Warp-inclusive scan of per-thread totals.
    unsigned long long incl = tot;
    #pragma unroll
    for (int o = 1; o < 32; o <<= 1) {
        unsigned long long n = __shfl_up_sync(0xffffffffu, incl, o);
        if (lane >= o) incl += n;
    }
    unsigned long long texcl = incl - tot;
    if (lane == 31) s_wtot[wid] = incl;
    __syncthreads();

    // Warp 0: scan the 8 warp totals; lane 7 stores the tile aggregate.
    if (wid == 0) {
        unsigned long long v = (lane < BLK / 32) ? s_wtot[lane] : 0ull;
        unsigned long long inc = v;
        #pragma unroll
        for (int o = 1; o < BLK / 32; o <<= 1) {
            unsigned long long n = __shfl_up_sync(0xffffffffu, inc, o);
            if (lane >= o) inc += n;
        }
        if (lane < BLK / 32) s_wexcl[lane] = inc - v;
        if (lane == BLK / 32 - 1) g_agg[bid] = inc;   // tile total
    }
    __syncthreads();

    // Per-batch metadata with TILE-LOCAL offsets.
    unsigned long long run = s_wexcl[wid] + texcl;    // local exclusive prefix
    #pragma unroll
    for (int k = 0; k < EPT; k++) {
        int i = i0 + k;
        if (i < B) {
            unsigned long long os = run & 0xffffffffull;   // local span prefix  (<2^20)
            unsigned long long ns = run >> 32;             // local filter prefix (<2^20)
            unsigned long long fv = p[k] >> 32;            // f (<2^10)
            g_meta[i] = os | (ns << 20) | (fv << 40);
            run += p[k];
        }
    }
}

// ---------------------------------------------------------------------------
// Copy: one warp per batch. Warp reconstructs its tile base from the 64
// tile aggregates (2 loads/lane + butterfly reduce), loads one packed u64
// of local metadata, then MLP-16 batched streaming copy.
// ---------------------------------------------------------------------------
__global__ void __launch_bounds__(256) copy_kernel(
        const float* __restrict__ src, float* __restrict__ out, int B) {
    int w    = (blockIdx.x * blockDim.x + threadIdx.x) >> 5;
    int lane = threadIdx.x & 31;
    if (w >= B) return;

    int tile = w >> 10;                       // TILE = 1024

    // Tile base = sum of aggregates of preceding tiles (MAXG = 64 entries).
    unsigned long long a0 = g_agg[lane];
    unsigned long long a1 = g_agg[lane + 32];
    unsigned long long v = 0;
    if (lane      < tile) v += a0;
    if (lane + 32 < tile) v += a1;
    #pragma unroll
    for (int o = 16; o > 0; o >>= 1)
        v += __shfl_xor_sync(0xffffffffu, v, o);   // base in all lanes
    int base_os = (int)(v & 0xffffffffull);
    int base_ns = (int)(v >> 32);

    unsigned long long m = g_meta[w];          // broadcast 8B load
    int f = (int)(m >> 40);
    if (f == 0) return;
    const float* s = src + base_os + (int)(m & 0xfffffull);
    float*       d = out + base_ns + (int)((m >> 20) & 0xfffffull);

    // All <=16 predicated streaming loads first (high MLP), then stores.
    float x[16];
    #pragma unroll
    for (int k = 0; k < 16; k++) {
        int i = lane + k * 32;
        x[k] = (i < f) ? __ldcs(s + i) : 0.0f;
    }
    #pragma unroll
    for (int k = 0; k < 16; k++) {
        int i = lane + k * 32;
        if (i < f) __stcs(d + i, x[k]);
    }
}

// ---------------------------------------------------------------------------
// Launch: 2 kernels, no memset, no cross-block waits anywhere.
// ---------------------------------------------------------------------------
extern "C" void kernel_launch(void* const* d_in, const int* in_sizes, int n_in,
                              void* d_out, int out_size) {
    const float* tgt_cache_loc = (const float*)d_in[0];
    const int*   accept_length = (const int*)d_in[1];
    const int*   accept_filter = (const int*)d_in[2];
    (void)n_in; (void)out_size;

    int B = in_sizes[1];
    int G = (B + TILE - 1) / TILE;

    scan_kernel<<<G, BLK>>>(accept_length, accept_filter, B);

    int blocks = (B * 32 + 255) / 256;    // one warp per batch
    copy_kernel<<<blocks, 256>>>(tgt_cache_loc, (float*)d_out, B);
}